// round 4
// baseline (speedup 1.0000x reference)
#include <cuda_runtime.h>
#include <cuda_bf16.h>
#include <cstdint>

// ---------------------------------------------------------------------------
// INT8Linear on sm_103 (no 'a'-features available at ptxas level -> no tcgen05).
// Exact int8 GEMM via mma.sync.m16n8k32.s8.s8.s32 (bit-exact s32 accumulate):
//   out[m][n] = (sum_k Xq[m][k]*Wq[n][k]) * xs[m] * ws[n] + bias[n]
// Inputs:  d_in[0] = x (8*4096*1024 f32), d_in[1] = weight (1024*1024 f32),
//          d_in[2] = bias (1024 f32).  Output: f32.
// ---------------------------------------------------------------------------

static constexpr int DIN   = 1024;
static constexpr int DOUT  = 1024;
static constexpr int MAX_M = 32768;

__device__ int8_t g_Xq[(size_t)MAX_M * DIN];   // 32 MB, row-major [M][K]
__device__ int8_t g_Wq[(size_t)DOUT  * DIN];   //  1 MB, row-major [N][K]
__device__ float  g_xs[MAX_M];
__device__ float  g_ws[DOUT];

// ============================ Quantizers ===================================
// One warp per row of 1024 floats; lane j-loop covers 8 strided float4s.
// scale = max(amax,1e-8)/127 ; q = clip(rint(v/scale),-128,127) -> int8
__device__ __forceinline__ void quant_row_warp(const float* __restrict__ src,
                                               int8_t* __restrict__ dq,
                                               float* __restrict__ ds,
                                               int row, int lane) {
    float4 v[8];
    const float4* s4 = reinterpret_cast<const float4*>(src + (size_t)row * 1024);
    #pragma unroll
    for (int j = 0; j < 8; j++) v[j] = s4[lane + 32 * j];

    float am = 0.0f;
    #pragma unroll
    for (int j = 0; j < 8; j++)
        am = fmaxf(am, fmaxf(fmaxf(fabsf(v[j].x), fabsf(v[j].y)),
                             fmaxf(fabsf(v[j].z), fabsf(v[j].w))));
    #pragma unroll
    for (int o = 16; o > 0; o >>= 1)
        am = fmaxf(am, __shfl_xor_sync(0xffffffffu, am, o));

    const float amax  = fmaxf(am, 1e-8f);
    const float scale = amax / 127.0f;
    if (lane == 0) ds[row] = scale;

    uint32_t* drow = reinterpret_cast<uint32_t*>(dq + (size_t)row * 1024);
    #pragma unroll
    for (int j = 0; j < 8; j++) {
        int q0 = (int)fminf(fmaxf(rintf(v[j].x / scale), -128.0f), 127.0f);
        int q1 = (int)fminf(fmaxf(rintf(v[j].y / scale), -128.0f), 127.0f);
        int q2 = (int)fminf(fmaxf(rintf(v[j].z / scale), -128.0f), 127.0f);
        int q3 = (int)fminf(fmaxf(rintf(v[j].w / scale), -128.0f), 127.0f);
        uint32_t pk = (uint32_t)(q0 & 0xff) | ((uint32_t)(q1 & 0xff) << 8) |
                      ((uint32_t)(q2 & 0xff) << 16) | ((uint32_t)(q3 & 0xff) << 24);
        drow[lane + 32 * j] = pk;
    }
}

__global__ __launch_bounds__(256) void quant_x_kernel(const float* __restrict__ x) {
    quant_row_warp(x, g_Xq, g_xs, blockIdx.x * 8 + (threadIdx.x >> 5), threadIdx.x & 31);
}
__global__ __launch_bounds__(256) void quant_w_kernel(const float* __restrict__ w) {
    quant_row_warp(w, g_Wq, g_ws, blockIdx.x * 8 + (threadIdx.x >> 5), threadIdx.x & 31);
}

// ============================ GEMM (int8 IMMA) =============================
// Tile 128x128, BK=64 bytes, 4-stage cp.async pipeline.
// 256 threads = 8 warps (2M x 4N); warp tile 64x32; mma.m16n8k32.s8.
#define BM 128
#define BN 128
#define BK 64
#define ASTRIDE 80                 // 64B row + 16B pad: ldmatrix conflict-free
#define STAGES 4
static constexpr uint32_t STAGE_A_BYTES = BM * ASTRIDE;           // 10240
static constexpr uint32_t STAGE_BYTES   = 2 * STAGE_A_BYTES;      // 20480
static constexpr uint32_t GEMM_SMEM     = STAGES * STAGE_BYTES;   // 81920

#define CP_ASYNC16(dst, src) \
    asm volatile("cp.async.cg.shared.global [%0], [%1], 16;" :: "r"(dst), "l"(src))
#define CP_COMMIT() asm volatile("cp.async.commit_group;" ::: "memory")
#define CP_WAIT2()  asm volatile("cp.async.wait_group 2;" ::: "memory")

__device__ __forceinline__ void load_stage(uint32_t s_base, const int8_t* a_g,
                                           const int8_t* b_g, int k0, int tid) {
    // A: 128 rows x 4 chunks of 16B ; B same. 4 chunks per thread.
    #pragma unroll
    for (int i = 0; i < 2; i++) {
        const int v = tid + 256 * i;
        const int r = v >> 2, c = (v & 3) * 16;
        CP_ASYNC16(s_base + r * ASTRIDE + c,
                   a_g + (size_t)r * DIN + k0 + c);
        CP_ASYNC16(s_base + STAGE_A_BYTES + r * ASTRIDE + c,
                   b_g + (size_t)r * DIN + k0 + c);
    }
}

__global__ __launch_bounds__(256, 2)
void gemm_imma_kernel(const float* __restrict__ bias, float* __restrict__ out) {
    extern __shared__ __align__(16) unsigned char smem[];
    const uint32_t sb = (uint32_t)__cvta_generic_to_shared(smem);

    const int tid  = threadIdx.x;
    const int warp = tid >> 5;
    const int lane = tid & 31;
    const int bm   = blockIdx.y * BM;
    const int bn   = blockIdx.x * BN;
    const int wm   = (warp & 1) * 64;
    const int wn   = (warp >> 1) * 32;

    const int8_t* a_g = g_Xq + (size_t)bm * DIN;
    const int8_t* b_g = g_Wq + (size_t)bn * DIN;

    int acc[4][4][4];
    #pragma unroll
    for (int im = 0; im < 4; im++)
        #pragma unroll
        for (int n = 0; n < 4; n++)
            #pragma unroll
            for (int r = 0; r < 4; r++) acc[im][n][r] = 0;

    // Prologue: fill stages 0..2
    #pragma unroll
    for (int p = 0; p < STAGES - 1; p++) {
        load_stage(sb + p * STAGE_BYTES, a_g, b_g, p * BK, tid);
        CP_COMMIT();
    }

    const int NKT = DIN / BK;  // 16
    #pragma unroll 1
    for (int kt = 0; kt < NKT; kt++) {
        CP_WAIT2();
        __syncthreads();

        // Prefetch stage kt+3 (overwrites stage of kt-1; safe after the sync)
        if (kt + STAGES - 1 < NKT)
            load_stage(sb + ((kt + STAGES - 1) % STAGES) * STAGE_BYTES,
                       a_g, b_g, (kt + STAGES - 1) * BK, tid);
        CP_COMMIT();

        const uint32_t sa = sb + (kt % STAGES) * STAGE_BYTES;
        const uint32_t sB = sa + STAGE_A_BYTES;

        #pragma unroll
        for (int ks = 0; ks < 2; ks++) {
            const int kb = ks * 32;
            uint32_t a[4][4], b[4][2];

            #pragma unroll
            for (int im = 0; im < 4; im++) {
                const int r  = wm + im * 16 + (lane & 15);
                const int cB = kb + (lane >> 4) * 16;
                asm volatile(
                    "ldmatrix.sync.aligned.m8n8.x4.shared.b16 {%0,%1,%2,%3}, [%4];"
                    : "=r"(a[im][0]), "=r"(a[im][1]), "=r"(a[im][2]), "=r"(a[im][3])
                    : "r"(sa + r * ASTRIDE + cB));
            }
            #pragma unroll
            for (int np = 0; np < 2; np++) {
                const int g   = lane >> 3;
                const int col = wn + np * 16 + (g >> 1) * 8 + (lane & 7);
                const int cB  = kb + (g & 1) * 16;
                asm volatile(
                    "ldmatrix.sync.aligned.m8n8.x4.shared.b16 {%0,%1,%2,%3}, [%4];"
                    : "=r"(b[2 * np][0]), "=r"(b[2 * np][1]),
                      "=r"(b[2 * np + 1][0]), "=r"(b[2 * np + 1][1])
                    : "r"(sB + col * ASTRIDE + cB));
            }
            #pragma unroll
            for (int im = 0; im < 4; im++) {
                #pragma unroll
                for (int n = 0; n < 4; n++) {
                    asm volatile(
                        "mma.sync.aligned.m16n8k32.row.col.s32.s8.s8.s32 "
                        "{%0,%1,%2,%3}, {%4,%5,%6,%7}, {%8,%9}, {%0,%1,%2,%3};"
                        : "+r"(acc[im][n][0]), "+r"(acc[im][n][1]),
                          "+r"(acc[im][n][2]), "+r"(acc[im][n][3])
                        : "r"(a[im][0]), "r"(a[im][1]), "r"(a[im][2]), "r"(a[im][3]),
                          "r"(b[n][0]), "r"(b[n][1]));
                }
            }
        }
        __syncthreads();
    }

    // Epilogue: dequant + bias (s32 -> f32 exact).
    #pragma unroll
    for (int im = 0; im < 4; im++) {
        const int row0 = bm + wm + im * 16 + (lane >> 2);
        const float xs0 = g_xs[row0];
        const float xs8 = g_xs[row0 + 8];
        #pragma unroll
        for (int n = 0; n < 4; n++) {
            const int col = bn + wn + n * 8 + (lane & 3) * 2;
            const float ws0 = g_ws[col],  ws1 = g_ws[col + 1];
            const float bb0 = bias[col],  bb1 = bias[col + 1];
            float2 o0, o1;
            o0.x = __int2float_rn(acc[im][n][0]) * xs0 * ws0 + bb0;
            o0.y = __int2float_rn(acc[im][n][1]) * xs0 * ws1 + bb1;
            o1.x = __int2float_rn(acc[im][n][2]) * xs8 * ws0 + bb0;
            o1.y = __int2float_rn(acc[im][n][3]) * xs8 * ws1 + bb1;
            *reinterpret_cast<float2*>(out + (size_t)row0 * DOUT + col)       = o0;
            *reinterpret_cast<float2*>(out + (size_t)(row0 + 8) * DOUT + col) = o1;
        }
    }
}

// ---------------------------------------------------------------------------
extern "C" void kernel_launch(void* const* d_in, const int* in_sizes, int n_in,
                              void* d_out, int out_size) {
    const float* x    = (const float*)d_in[0];
    const float* w    = (const float*)d_in[1];
    const float* bias = (const float*)d_in[2];
    float* out        = (float*)d_out;

    const int M = in_sizes[0] / DIN;  // 32768

    quant_w_kernel<<<DOUT / 8, 256>>>(w);
    quant_x_kernel<<<M / 8, 256>>>(x);

    cudaFuncSetAttribute(gemm_imma_kernel,
                         cudaFuncAttributeMaxDynamicSharedMemorySize, GEMM_SMEM);
    dim3 grid(DOUT / BN, M / BM);  // (8, 256)
    gemm_imma_kernel<<<grid, 256, GEMM_SMEM>>>(bias, out);
}

// round 5
// speedup vs baseline: 1.2936x; 1.2936x over previous
#include <cuda_runtime.h>
#include <cuda_bf16.h>
#include <cstdint>

// ---------------------------------------------------------------------------
// INT8Linear on sm_103 (ptxas target has no 'a' features -> no tcgen05,
// and legacy int8 IMMA is de-rated). Exact int8 GEMM emulated with bf16
// mma.sync.m16n8k16 (int8 values exact in bf16; K=1024 integer partial sums
// < 2^24 so fp32 accumulation is exact):
//   out[m][n] = (sum_k Xq[m][k]*Wq[n][k]) * xs[m] * ws[n] + bias[n]
// ---------------------------------------------------------------------------

static constexpr int DIN   = 1024;
static constexpr int DOUT  = 1024;
static constexpr int MAX_M = 32768;

__device__ __nv_bfloat16 g_Xq[(size_t)MAX_M * DIN];   // 64 MB row-major [M][K]
__device__ __nv_bfloat16 g_Wq[(size_t)DOUT  * DIN];   //  2 MB row-major [N][K]
__device__ float         g_xs[MAX_M];
__device__ float         g_ws[DOUT];

// ============================ Quantizers ===================================
// One warp per row of 1024 floats. scale = max(amax,1e-8)/127,
// q = clip(rint(v/scale),-128,127) stored as bf16 (exact).
__device__ __forceinline__ void quant_row_warp(const float* __restrict__ src,
                                               __nv_bfloat16* __restrict__ dq,
                                               float* __restrict__ ds,
                                               int row, int lane) {
    float4 v[8];
    const float4* s4 = reinterpret_cast<const float4*>(src + (size_t)row * 1024);
    #pragma unroll
    for (int j = 0; j < 8; j++) v[j] = s4[lane + 32 * j];

    float am = 0.0f;
    #pragma unroll
    for (int j = 0; j < 8; j++)
        am = fmaxf(am, fmaxf(fmaxf(fabsf(v[j].x), fabsf(v[j].y)),
                             fmaxf(fabsf(v[j].z), fabsf(v[j].w))));
    #pragma unroll
    for (int o = 16; o > 0; o >>= 1)
        am = fmaxf(am, __shfl_xor_sync(0xffffffffu, am, o));

    const float amax  = fmaxf(am, 1e-8f);
    const float scale = amax / 127.0f;
    if (lane == 0) ds[row] = scale;

    uint2* drow = reinterpret_cast<uint2*>(dq + (size_t)row * 1024);
    #pragma unroll
    for (int j = 0; j < 8; j++) {
        float q0 = fminf(fmaxf(rintf(v[j].x / scale), -128.0f), 127.0f);
        float q1 = fminf(fmaxf(rintf(v[j].y / scale), -128.0f), 127.0f);
        float q2 = fminf(fmaxf(rintf(v[j].z / scale), -128.0f), 127.0f);
        float q3 = fminf(fmaxf(rintf(v[j].w / scale), -128.0f), 127.0f);
        __nv_bfloat162 p0 = __floats2bfloat162_rn(q0, q1);
        __nv_bfloat162 p1 = __floats2bfloat162_rn(q2, q3);
        uint2 pk;
        pk.x = *reinterpret_cast<uint32_t*>(&p0);
        pk.y = *reinterpret_cast<uint32_t*>(&p1);
        drow[lane + 32 * j] = pk;
    }
}

__global__ __launch_bounds__(256) void quant_x_kernel(const float* __restrict__ x) {
    quant_row_warp(x, g_Xq, g_xs, blockIdx.x * 8 + (threadIdx.x >> 5), threadIdx.x & 31);
}
__global__ __launch_bounds__(256) void quant_w_kernel(const float* __restrict__ w) {
    quant_row_warp(w, g_Wq, g_ws, blockIdx.x * 8 + (threadIdx.x >> 5), threadIdx.x & 31);
}

// ============================ GEMM (bf16 HMMA) =============================
// Tile 128x128, BK=32 (64B rows), 4-stage cp.async pipeline.
// 256 threads = 8 warps (2M x 4N); warp tile 64x32; mma.m16n8k16.bf16.
#define BM 128
#define BN 128
#define BK 32
#define ASTRIDE 80                 // 64B row + 16B pad -> ldmatrix conflict-free
#define STAGES 4
static constexpr uint32_t STAGE_A_BYTES = BM * ASTRIDE;          // 10240
static constexpr uint32_t STAGE_BYTES   = 2 * STAGE_A_BYTES;     // 20480
static constexpr uint32_t GEMM_SMEM     = STAGES * STAGE_BYTES;  // 81920

#define CP_ASYNC16(dst, src) \
    asm volatile("cp.async.cg.shared.global [%0], [%1], 16;" :: "r"(dst), "l"(src))
#define CP_COMMIT() asm volatile("cp.async.commit_group;" ::: "memory")
#define CP_WAIT2()  asm volatile("cp.async.wait_group 2;" ::: "memory")

__device__ __forceinline__ void load_stage(uint32_t s_base,
                                           const __nv_bfloat16* a_g,
                                           const __nv_bfloat16* b_g,
                                           int k0, int tid) {
    // A: 128 rows x 4 chunks of 16B; B same. 2+2 chunks per thread.
    #pragma unroll
    for (int i = 0; i < 2; i++) {
        const int v = tid + 256 * i;
        const int r = v >> 2, c = (v & 3) * 16;   // c = byte offset in 64B row
        CP_ASYNC16(s_base + r * ASTRIDE + c,
                   (const char*)(a_g + (size_t)r * DIN + k0) + c);
        CP_ASYNC16(s_base + STAGE_A_BYTES + r * ASTRIDE + c,
                   (const char*)(b_g + (size_t)r * DIN + k0) + c);
    }
}

__global__ __launch_bounds__(256, 2)
void gemm_hmma_kernel(const float* __restrict__ bias, float* __restrict__ out) {
    extern __shared__ __align__(16) unsigned char smem[];
    const uint32_t sb = (uint32_t)__cvta_generic_to_shared(smem);

    const int tid  = threadIdx.x;
    const int warp = tid >> 5;
    const int lane = tid & 31;
    const int bm   = blockIdx.y * BM;
    const int bn   = blockIdx.x * BN;
    const int wm   = (warp & 1) * 64;
    const int wn   = (warp >> 1) * 32;

    const __nv_bfloat16* a_g = g_Xq + (size_t)bm * DIN;
    const __nv_bfloat16* b_g = g_Wq + (size_t)bn * DIN;

    float acc[4][4][4];
    #pragma unroll
    for (int im = 0; im < 4; im++)
        #pragma unroll
        for (int n = 0; n < 4; n++)
            #pragma unroll
            for (int r = 0; r < 4; r++) acc[im][n][r] = 0.0f;

    #pragma unroll
    for (int p = 0; p < STAGES - 1; p++) {
        load_stage(sb + p * STAGE_BYTES, a_g, b_g, p * BK, tid);
        CP_COMMIT();
    }

    const int NKT = DIN / BK;  // 32
    #pragma unroll 1
    for (int kt = 0; kt < NKT; kt++) {
        CP_WAIT2();
        __syncthreads();

        if (kt + STAGES - 1 < NKT)
            load_stage(sb + ((kt + STAGES - 1) % STAGES) * STAGE_BYTES,
                       a_g, b_g, (kt + STAGES - 1) * BK, tid);
        CP_COMMIT();

        const uint32_t sa = sb + (kt % STAGES) * STAGE_BYTES;
        const uint32_t sB = sa + STAGE_A_BYTES;

        #pragma unroll
        for (int ks = 0; ks < 2; ks++) {
            const int kb = ks * 32;                 // byte offset of 16-elem group
            uint32_t a[4][4], b[4][2];

            #pragma unroll
            for (int im = 0; im < 4; im++) {
                const int r = wm + im * 16 + (lane & 15);
                asm volatile(
                    "ldmatrix.sync.aligned.m8n8.x4.shared.b16 {%0,%1,%2,%3}, [%4];"
                    : "=r"(a[im][0]), "=r"(a[im][1]), "=r"(a[im][2]), "=r"(a[im][3])
                    : "r"(sa + r * ASTRIDE + kb + (lane >> 4) * 16));
            }
            #pragma unroll
            for (int np = 0; np < 2; np++) {
                const int g   = lane >> 3;
                const int col = wn + np * 16 + (g >> 1) * 8 + (lane & 7);
                asm volatile(
                    "ldmatrix.sync.aligned.m8n8.x4.shared.b16 {%0,%1,%2,%3}, [%4];"
                    : "=r"(b[2 * np][0]), "=r"(b[2 * np][1]),
                      "=r"(b[2 * np + 1][0]), "=r"(b[2 * np + 1][1])
                    : "r"(sB + col * ASTRIDE + kb + (g & 1) * 16));
            }
            #pragma unroll
            for (int im = 0; im < 4; im++) {
                #pragma unroll
                for (int n = 0; n < 4; n++) {
                    asm volatile(
                        "mma.sync.aligned.m16n8k16.row.col.f32.bf16.bf16.f32 "
                        "{%0,%1,%2,%3}, {%4,%5,%6,%7}, {%8,%9}, {%0,%1,%2,%3};"
                        : "+f"(acc[im][n][0]), "+f"(acc[im][n][1]),
                          "+f"(acc[im][n][2]), "+f"(acc[im][n][3])
                        : "r"(a[im][0]), "r"(a[im][1]), "r"(a[im][2]), "r"(a[im][3]),
                          "r"(b[n][0]), "r"(b[n][1]));
                }
            }
        }
        __syncthreads();
    }

    // Epilogue: dequant + bias.
    #pragma unroll
    for (int im = 0; im < 4; im++) {
        const int row0 = bm + wm + im * 16 + (lane >> 2);
        const float xs0 = g_xs[row0];
        const float xs8 = g_xs[row0 + 8];
        #pragma unroll
        for (int n = 0; n < 4; n++) {
            const int col = bn + wn + n * 8 + (lane & 3) * 2;
            const float ws0 = g_ws[col],  ws1 = g_ws[col + 1];
            const float bb0 = bias[col],  bb1 = bias[col + 1];
            float2 o0, o1;
            o0.x = acc[im][n][0] * xs0 * ws0 + bb0;
            o0.y = acc[im][n][1] * xs0 * ws1 + bb1;
            o1.x = acc[im][n][2] * xs8 * ws0 + bb0;
            o1.y = acc[im][n][3] * xs8 * ws1 + bb1;
            *reinterpret_cast<float2*>(out + (size_t)row0 * DOUT + col)       = o0;
            *reinterpret_cast<float2*>(out + (size_t)(row0 + 8) * DOUT + col) = o1;
        }
    }
}

// ---------------------------------------------------------------------------
extern "C" void kernel_launch(void* const* d_in, const int* in_sizes, int n_in,
                              void* d_out, int out_size) {
    const float* x    = (const float*)d_in[0];
    const float* w    = (const float*)d_in[1];
    const float* bias = (const float*)d_in[2];
    float* out        = (float*)d_out;

    const int M = in_sizes[0] / DIN;  // 32768

    quant_w_kernel<<<DOUT / 8, 256>>>(w);
    quant_x_kernel<<<M / 8, 256>>>(x);

    cudaFuncSetAttribute(gemm_hmma_kernel,
                         cudaFuncAttributeMaxDynamicSharedMemorySize, GEMM_SMEM);
    dim3 grid(DOUT / BN, M / BM);  // (8, 256)
    gemm_hmma_kernel<<<grid, 256, GEMM_SMEM>>>(bias, out);
}

// round 7
// speedup vs baseline: 2.1958x; 1.6974x over previous
#include <cuda_runtime.h>
#include <cuda_bf16.h>
#include <cstdint>

// ---------------------------------------------------------------------------
// INT8Linear on sm_103 (ptxas target lacks 'a' features -> no tcgen05; legacy
// int8 IMMA measured 4x slower than bf16 HMMA). Exact int8 GEMM emulated with
// bf16 mma.sync.m16n8k16 (int8 exact in bf16; K=1024 integer partial sums
// < 2^24 so fp32 accumulation is exact):
//   out[m][n] = (sum_k Xq[m][k]*Wq[n][k]) * xs[m] * ws[n] + bias[n]
// R1 config (BK=64, 144B stride) + 2-stage cp.async double buffering.
// ---------------------------------------------------------------------------

static constexpr int DIN   = 1024;
static constexpr int DOUT  = 1024;
static constexpr int MAX_M = 32768;

__device__ __nv_bfloat16 g_Xq[(size_t)MAX_M * DIN];   // 64 MB row-major [M][K]
__device__ __nv_bfloat16 g_Wq[(size_t)DOUT  * DIN];   //  2 MB row-major [N][K]
__device__ float         g_xs[MAX_M];
__device__ float         g_ws[DOUT];

// ============================ Quantizers ===================================
// One warp per row of 1024 floats. scale = max(amax,1e-8)/127,
// q = clip(rint(v/scale),-128,127) stored as bf16 (exact).
__device__ __forceinline__ void quant_row_warp(const float* __restrict__ src,
                                               __nv_bfloat16* __restrict__ dq,
                                               float* __restrict__ ds,
                                               int row, int lane) {
    float4 v[8];
    const float4* s4 = reinterpret_cast<const float4*>(src + (size_t)row * 1024);
    #pragma unroll
    for (int j = 0; j < 8; j++) v[j] = s4[lane + 32 * j];

    float am = 0.0f;
    #pragma unroll
    for (int j = 0; j < 8; j++)
        am = fmaxf(am, fmaxf(fmaxf(fabsf(v[j].x), fabsf(v[j].y)),
                             fmaxf(fabsf(v[j].z), fabsf(v[j].w))));
    #pragma unroll
    for (int o = 16; o > 0; o >>= 1)
        am = fmaxf(am, __shfl_xor_sync(0xffffffffu, am, o));

    const float amax  = fmaxf(am, 1e-8f);
    const float scale = amax / 127.0f;
    if (lane == 0) ds[row] = scale;

    uint2* drow = reinterpret_cast<uint2*>(dq + (size_t)row * 1024);
    #pragma unroll
    for (int j = 0; j < 8; j++) {
        float q0 = fminf(fmaxf(rintf(v[j].x / scale), -128.0f), 127.0f);
        float q1 = fminf(fmaxf(rintf(v[j].y / scale), -128.0f), 127.0f);
        float q2 = fminf(fmaxf(rintf(v[j].z / scale), -128.0f), 127.0f);
        float q3 = fminf(fmaxf(rintf(v[j].w / scale), -128.0f), 127.0f);
        __nv_bfloat162 p0 = __floats2bfloat162_rn(q0, q1);
        __nv_bfloat162 p1 = __floats2bfloat162_rn(q2, q3);
        uint2 pk;
        pk.x = *reinterpret_cast<uint32_t*>(&p0);
        pk.y = *reinterpret_cast<uint32_t*>(&p1);
        drow[lane + 32 * j] = pk;
    }
}

__global__ __launch_bounds__(256) void quant_x_kernel(const float* __restrict__ x) {
    quant_row_warp(x, g_Xq, g_xs, blockIdx.x * 8 + (threadIdx.x >> 5), threadIdx.x & 31);
}
__global__ __launch_bounds__(256) void quant_w_kernel(const float* __restrict__ w) {
    quant_row_warp(w, g_Wq, g_ws, blockIdx.x * 8 + (threadIdx.x >> 5), threadIdx.x & 31);
}

// ============================ GEMM (bf16 HMMA) =============================
// Tile 128x128, BK=64 (128B rows + 16B pad = 144B stride), 2-stage cp.async.
// 256 threads = 8 warps (2M x 4N); warp tile 64x32; mma.m16n8k16.bf16.
#define BM 128
#define BN 128
#define BK 64
#define ASTRIDE 144                 // 128B data + 16B pad: conflict-free
static constexpr uint32_t STAGE_A_BYTES = BM * ASTRIDE;          // 18432
static constexpr uint32_t STAGE_BYTES   = 2 * STAGE_A_BYTES;     // 36864
static constexpr uint32_t GEMM_SMEM     = 2 * STAGE_BYTES;       // 73728

#define CP_ASYNC16(dst, src) \
    asm volatile("cp.async.cg.shared.global [%0], [%1], 16;" :: "r"(dst), "l"(src))
#define CP_COMMIT() asm volatile("cp.async.commit_group;" ::: "memory")
#define CP_WAIT0()  asm volatile("cp.async.wait_group 0;" ::: "memory")

__device__ __forceinline__ void load_stage(uint32_t s_base,
                                           const __nv_bfloat16* a_g,
                                           const __nv_bfloat16* b_g,
                                           int k0, int tid) {
    // A: 128 rows x 8 chunks of 16B; B same. 4+4 chunks per thread.
    #pragma unroll
    for (int i = 0; i < 4; i++) {
        const int v = tid + 256 * i;
        const int r = v >> 3;
        const int c = (v & 7) * 16;   // byte offset within 128B row
        CP_ASYNC16(s_base + r * ASTRIDE + c,
                   (const char*)(a_g + (size_t)r * DIN + k0) + c);
        CP_ASYNC16(s_base + STAGE_A_BYTES + r * ASTRIDE + c,
                   (const char*)(b_g + (size_t)r * DIN + k0) + c);
    }
}

__global__ __launch_bounds__(256, 2)
void gemm_hmma_kernel(const float* __restrict__ bias, float* __restrict__ out) {
    extern __shared__ __align__(16) unsigned char smem[];
    const uint32_t sb = (uint32_t)__cvta_generic_to_shared(smem);

    const int tid  = threadIdx.x;
    const int warp = tid >> 5;
    const int lane = tid & 31;
    const int bm   = blockIdx.y * BM;
    const int bn   = blockIdx.x * BN;
    const int wm   = (warp & 1) * 64;
    const int wn   = (warp >> 1) * 32;

    const __nv_bfloat16* a_g = g_Xq + (size_t)bm * DIN;
    const __nv_bfloat16* b_g = g_Wq + (size_t)bn * DIN;

    float acc[4][4][4];
    #pragma unroll
    for (int im = 0; im < 4; im++)
        #pragma unroll
        for (int n = 0; n < 4; n++)
            #pragma unroll
            for (int r = 0; r < 4; r++) acc[im][n][r] = 0.0f;

    // Prologue: stage 0
    load_stage(sb, a_g, b_g, 0, tid);
    CP_COMMIT();

    const int NKT = DIN / BK;  // 16
    #pragma unroll 1
    for (int kt = 0; kt < NKT; kt++) {
        CP_WAIT0();
        __syncthreads();

        if (kt + 1 < NKT) {
            load_stage(sb + ((kt + 1) & 1) * STAGE_BYTES, a_g, b_g,
                       (kt + 1) * BK, tid);
            CP_COMMIT();
        }

        const uint32_t sa = sb + (kt & 1) * STAGE_BYTES;
        const uint32_t sB = sa + STAGE_A_BYTES;

        #pragma unroll
        for (int ks = 0; ks < 4; ks++) {
            const int kb = ks * 32;                 // byte offset of k16 group
            uint32_t a[4][4], b[4][2];

            #pragma unroll
            for (int im = 0; im < 4; im++) {
                const int r = wm + im * 16 + (lane & 15);
                asm volatile(
                    "ldmatrix.sync.aligned.m8n8.x4.shared.b16 {%0,%1,%2,%3}, [%4];"
                    : "=r"(a[im][0]), "=r"(a[im][1]), "=r"(a[im][2]), "=r"(a[im][3])
                    : "r"(sa + r * ASTRIDE + kb + (lane >> 4) * 16));
            }
            #pragma unroll
            for (int np = 0; np < 2; np++) {
                const int g   = lane >> 3;
                const int col = wn + np * 16 + (g >> 1) * 8 + (lane & 7);
                asm volatile(
                    "ldmatrix.sync.aligned.m8n8.x4.shared.b16 {%0,%1,%2,%3}, [%4];"
                    : "=r"(b[2 * np][0]), "=r"(b[2 * np][1]),
                      "=r"(b[2 * np + 1][0]), "=r"(b[2 * np + 1][1])
                    : "r"(sB + col * ASTRIDE + kb + (g & 1) * 16));
            }
            #pragma unroll
            for (int im = 0; im < 4; im++) {
                #pragma unroll
                for (int n = 0; n < 4; n++) {
                    asm volatile(
                        "mma.sync.aligned.m16n8k16.row.col.f32.bf16.bf16.f32 "
                        "{%0,%1,%2,%3}, {%4,%5,%6,%7}, {%8,%9}, {%0,%1,%2,%3};"
                        : "+f"(acc[im][n][0]), "+f"(acc[im][n][1]),
                          "+f"(acc[im][n][2]), "+f"(acc[im][n][3])
                        : "r"(a[im][0]), "r"(a[im][1]), "r"(a[im][2]), "r"(a[im][3]),
                          "r"(b[n][0]), "r"(b[n][1]));
                }
            }
        }
        __syncthreads();
    }

    // Epilogue: dequant + bias.
    #pragma unroll
    for (int im = 0; im < 4; im++) {
        const int row0 = bm + wm + im * 16 + (lane >> 2);
        const float xs0 = g_xs[row0];
        const float xs8 = g_xs[row0 + 8];
        #pragma unroll
        for (int n = 0; n < 4; n++) {
            const int col = bn + wn + n * 8 + (lane & 3) * 2;
            const float ws0 = g_ws[col],  ws1 = g_ws[col + 1];
            const float bb0 = bias[col],  bb1 = bias[col + 1];
            float2 o0, o1;
            o0.x = acc[im][n][0] * xs0 * ws0 + bb0;
            o0.y = acc[im][n][1] * xs0 * ws1 + bb1;
            o1.x = acc[im][n][2] * xs8 * ws0 + bb0;
            o1.y = acc[im][n][3] * xs8 * ws1 + bb1;
            *reinterpret_cast<float2*>(out + (size_t)row0 * DOUT + col)       = o0;
            *reinterpret_cast<float2*>(out + (size_t)(row0 + 8) * DOUT + col) = o1;
        }
    }
}

// ---------------------------------------------------------------------------
extern "C" void kernel_launch(void* const* d_in, const int* in_sizes, int n_in,
                              void* d_out, int out_size) {
    const float* x    = (const float*)d_in[0];
    const float* w    = (const float*)d_in[1];
    const float* bias = (const float*)d_in[2];
    float* out        = (float*)d_out;

    const int M = in_sizes[0] / DIN;  // 32768

    quant_w_kernel<<<DOUT / 8, 256>>>(w);
    quant_x_kernel<<<M / 8, 256>>>(x);

    cudaFuncSetAttribute(gemm_hmma_kernel,
                         cudaFuncAttributeMaxDynamicSharedMemorySize, GEMM_SMEM);
    dim3 grid(DOUT / BN, M / BM);  // (8, 256)
    gemm_hmma_kernel<<<grid, 256, GEMM_SMEM>>>(bias, out);
}

// round 8
// speedup vs baseline: 2.4277x; 1.1056x over previous
#include <cuda_runtime.h>
#include <cuda_bf16.h>
#include <cstdint>

// ---------------------------------------------------------------------------
// INT8Linear on sm_103 (no tcgen05 at this ptxas target; legacy int8 IMMA is
// de-rated). Exact int8 GEMM emulated with bf16 mma.sync.m16n8k16 (int8 exact
// in bf16; K=1024 integer partial sums < 2^24 -> exact fp32 accumulation):
//   out[m][n] = (sum_k Xq[m][k]*Wq[n][k]) * xs[m] * ws[n] + bias[n]
// GEMM: 128x128 tile, BK=64, 3-stage cp.async pipeline, XOR-swizzled SMEM
// (no padding), wait_group 1, one __syncthreads per K-iteration.
// ---------------------------------------------------------------------------

static constexpr int DIN   = 1024;
static constexpr int DOUT  = 1024;
static constexpr int MAX_M = 32768;

__device__ __nv_bfloat16 g_Xq[(size_t)MAX_M * DIN];   // 64 MB row-major [M][K]
__device__ __nv_bfloat16 g_Wq[(size_t)DOUT  * DIN];   //  2 MB row-major [N][K]
__device__ float         g_xs[MAX_M];
__device__ float         g_ws[DOUT];

// ============================ Quantizers ===================================
__device__ __forceinline__ void quant_row_warp(const float* __restrict__ src,
                                               __nv_bfloat16* __restrict__ dq,
                                               float* __restrict__ ds,
                                               int row, int lane) {
    float4 v[8];
    const float4* s4 = reinterpret_cast<const float4*>(src + (size_t)row * 1024);
    #pragma unroll
    for (int j = 0; j < 8; j++) v[j] = s4[lane + 32 * j];

    float am = 0.0f;
    #pragma unroll
    for (int j = 0; j < 8; j++)
        am = fmaxf(am, fmaxf(fmaxf(fabsf(v[j].x), fabsf(v[j].y)),
                             fmaxf(fabsf(v[j].z), fabsf(v[j].w))));
    #pragma unroll
    for (int o = 16; o > 0; o >>= 1)
        am = fmaxf(am, __shfl_xor_sync(0xffffffffu, am, o));

    const float amax  = fmaxf(am, 1e-8f);
    const float scale = amax / 127.0f;
    if (lane == 0) ds[row] = scale;

    uint2* drow = reinterpret_cast<uint2*>(dq + (size_t)row * 1024);
    #pragma unroll
    for (int j = 0; j < 8; j++) {
        float q0 = fminf(fmaxf(rintf(v[j].x / scale), -128.0f), 127.0f);
        float q1 = fminf(fmaxf(rintf(v[j].y / scale), -128.0f), 127.0f);
        float q2 = fminf(fmaxf(rintf(v[j].z / scale), -128.0f), 127.0f);
        float q3 = fminf(fmaxf(rintf(v[j].w / scale), -128.0f), 127.0f);
        __nv_bfloat162 p0 = __floats2bfloat162_rn(q0, q1);
        __nv_bfloat162 p1 = __floats2bfloat162_rn(q2, q3);
        uint2 pk;
        pk.x = *reinterpret_cast<uint32_t*>(&p0);
        pk.y = *reinterpret_cast<uint32_t*>(&p1);
        drow[lane + 32 * j] = pk;
    }
}

__global__ __launch_bounds__(256) void quant_x_kernel(const float* __restrict__ x) {
    quant_row_warp(x, g_Xq, g_xs, blockIdx.x * 8 + (threadIdx.x >> 5), threadIdx.x & 31);
}
__global__ __launch_bounds__(256) void quant_w_kernel(const float* __restrict__ w) {
    quant_row_warp(w, g_Wq, g_ws, blockIdx.x * 8 + (threadIdx.x >> 5), threadIdx.x & 31);
}

// ============================ GEMM (bf16 HMMA) =============================
#define BM 128
#define BN 128
#define BK 64
#define STAGES 3
// Swizzled rows: 128B/row, byte col c -> c ^ ((r & 7) * 16). No padding.
static constexpr uint32_t STAGE_A_BYTES = BM * 128;              // 16384
static constexpr uint32_t STAGE_BYTES   = 2 * STAGE_A_BYTES;     // 32768
static constexpr uint32_t GEMM_SMEM     = STAGES * STAGE_BYTES;  // 98304

#define CP_ASYNC16(dst, src) \
    asm volatile("cp.async.cg.shared.global [%0], [%1], 16;" :: "r"(dst), "l"(src))
#define CP_COMMIT() asm volatile("cp.async.commit_group;" ::: "memory")
#define CP_WAIT1()  asm volatile("cp.async.wait_group 1;" ::: "memory")

__device__ __forceinline__ void load_stage(uint32_t s_base,
                                           const __nv_bfloat16* a_g,
                                           const __nv_bfloat16* b_g,
                                           int k0, int tid) {
    // A: 128 rows x 8 chunks of 16B (swizzled); B same. 4+4 chunks/thread.
    #pragma unroll
    for (int i = 0; i < 4; i++) {
        const int v = tid + 256 * i;
        const int r = v >> 3;
        const int c = (v & 7) * 16;                       // byte col in row
        const uint32_t sc = (uint32_t)(c ^ ((r & 7) * 16));
        CP_ASYNC16(s_base + r * 128 + sc,
                   (const char*)(a_g + (size_t)r * DIN + k0) + c);
        CP_ASYNC16(s_base + STAGE_A_BYTES + r * 128 + sc,
                   (const char*)(b_g + (size_t)r * DIN + k0) + c);
    }
}

__global__ __launch_bounds__(256, 2)
void gemm_hmma_kernel(const float* __restrict__ bias, float* __restrict__ out) {
    extern __shared__ __align__(16) unsigned char smem[];
    const uint32_t sb = (uint32_t)__cvta_generic_to_shared(smem);

    const int tid  = threadIdx.x;
    const int warp = tid >> 5;
    const int lane = tid & 31;
    const int bm   = blockIdx.y * BM;
    const int bn   = blockIdx.x * BN;
    const int wm   = (warp & 1) * 64;
    const int wn   = (warp >> 1) * 32;

    const __nv_bfloat16* a_g = g_Xq + (size_t)bm * DIN;
    const __nv_bfloat16* b_g = g_Wq + (size_t)bn * DIN;

    float acc[4][4][4];
    #pragma unroll
    for (int im = 0; im < 4; im++)
        #pragma unroll
        for (int n = 0; n < 4; n++)
            #pragma unroll
            for (int r = 0; r < 4; r++) acc[im][n][r] = 0.0f;

    // Prologue: stages 0, 1
    load_stage(sb + 0 * STAGE_BYTES, a_g, b_g, 0 * BK, tid);
    CP_COMMIT();
    load_stage(sb + 1 * STAGE_BYTES, a_g, b_g, 1 * BK, tid);
    CP_COMMIT();

    const int NKT = DIN / BK;  // 16
    #pragma unroll 1
    for (int kt = 0; kt < NKT; kt++) {
        CP_WAIT1();              // stage kt complete (one newer may pend)
        __syncthreads();         // all warps done reading stage (kt+2)%3

        const int kp = kt + 2;   // prefetch stage kt+2
        if (kp < NKT)
            load_stage(sb + (kp % STAGES) * STAGE_BYTES, a_g, b_g, kp * BK, tid);
        CP_COMMIT();             // uniform commits keep wait_group semantics

        const uint32_t sa = sb + (kt % STAGES) * STAGE_BYTES;
        const uint32_t sB = sa + STAGE_A_BYTES;

        #pragma unroll
        for (int ks = 0; ks < 4; ks++) {
            const int kb = ks * 32;          // byte col of 16-elem K group
            uint32_t a[4][4], b[4][2];

            #pragma unroll
            for (int im = 0; im < 4; im++) {
                const int r = wm + im * 16 + (lane & 15);
                const int c = kb + (lane >> 4) * 16;
                asm volatile(
                    "ldmatrix.sync.aligned.m8n8.x4.shared.b16 {%0,%1,%2,%3}, [%4];"
                    : "=r"(a[im][0]), "=r"(a[im][1]), "=r"(a[im][2]), "=r"(a[im][3])
                    : "r"(sa + r * 128 + (uint32_t)(c ^ ((r & 7) * 16))));
            }
            #pragma unroll
            for (int np = 0; np < 2; np++) {
                const int g   = lane >> 3;
                const int col = wn + np * 16 + (g >> 1) * 8 + (lane & 7);
                const int c   = kb + (g & 1) * 16;
                asm volatile(
                    "ldmatrix.sync.aligned.m8n8.x4.shared.b16 {%0,%1,%2,%3}, [%4];"
                    : "=r"(b[2 * np][0]), "=r"(b[2 * np][1]),
                      "=r"(b[2 * np + 1][0]), "=r"(b[2 * np + 1][1])
                    : "r"(sB + col * 128 + (uint32_t)(c ^ ((col & 7) * 16))));
            }
            #pragma unroll
            for (int im = 0; im < 4; im++) {
                #pragma unroll
                for (int n = 0; n < 4; n++) {
                    asm volatile(
                        "mma.sync.aligned.m16n8k16.row.col.f32.bf16.bf16.f32 "
                        "{%0,%1,%2,%3}, {%4,%5,%6,%7}, {%8,%9}, {%0,%1,%2,%3};"
                        : "+f"(acc[im][n][0]), "+f"(acc[im][n][1]),
                          "+f"(acc[im][n][2]), "+f"(acc[im][n][3])
                        : "r"(a[im][0]), "r"(a[im][1]), "r"(a[im][2]), "r"(a[im][3]),
                          "r"(b[n][0]), "r"(b[n][1]));
                }
            }
        }
        // no bottom barrier: next iteration's top barrier is the fence
    }

    // Epilogue: dequant + bias.
    #pragma unroll
    for (int im = 0; im < 4; im++) {
        const int row0 = bm + wm + im * 16 + (lane >> 2);
        const float xs0 = g_xs[row0];
        const float xs8 = g_xs[row0 + 8];
        #pragma unroll
        for (int n = 0; n < 4; n++) {
            const int col = bn + wn + n * 8 + (lane & 3) * 2;
            const float ws0 = g_ws[col],  ws1 = g_ws[col + 1];
            const float bb0 = bias[col],  bb1 = bias[col + 1];
            float2 o0, o1;
            o0.x = acc[im][n][0] * xs0 * ws0 + bb0;
            o0.y = acc[im][n][1] * xs0 * ws1 + bb1;
            o1.x = acc[im][n][2] * xs8 * ws0 + bb0;
            o1.y = acc[im][n][3] * xs8 * ws1 + bb1;
            *reinterpret_cast<float2*>(out + (size_t)row0 * DOUT + col)       = o0;
            *reinterpret_cast<float2*>(out + (size_t)(row0 + 8) * DOUT + col) = o1;
        }
    }
}

// ---------------------------------------------------------------------------
extern "C" void kernel_launch(void* const* d_in, const int* in_sizes, int n_in,
                              void* d_out, int out_size) {
    const float* x    = (const float*)d_in[0];
    const float* w    = (const float*)d_in[1];
    const float* bias = (const float*)d_in[2];
    float* out        = (float*)d_out;

    const int M = in_sizes[0] / DIN;  // 32768

    quant_w_kernel<<<DOUT / 8, 256>>>(w);
    quant_x_kernel<<<M / 8, 256>>>(x);

    cudaFuncSetAttribute(gemm_hmma_kernel,
                         cudaFuncAttributeMaxDynamicSharedMemorySize, GEMM_SMEM);
    dim3 grid(DOUT / BN, M / BM);  // (8, 256)
    gemm_hmma_kernel<<<grid, 256, GEMM_SMEM>>>(bias, out);
}